// round 1
// baseline (speedup 1.0000x reference)
#include <cuda_runtime.h>

// Problem dims (fixed by the dataset)
#define N_   64
#define C_   64
#define T_   300
#define V_   25
#define S_   3
#define K_   192            // S_*C_
#define TT   4              // t positions per block
#define COLS 100            // TT*V_
#define TBLK 75             // T_/TT
#define NTHREADS 256

// Packed/folded parameters (written by prep kernel each launch)
__device__ __align__(16) float g_Wt[K_ * 64];          // [k][o], k = s*64+c
__device__ __align__(16) float g_AeP[S_ * V_ * 26];    // [s][v][26] padded
__device__ __align__(16) float g_alpha[C_];
__device__ __align__(16) float g_bshift[C_];

// ---------------- f32x2 helpers (Blackwell packed fp32) ----------------
__device__ __forceinline__ unsigned long long splat2(float x) {
    unsigned long long r;
    asm("mov.b64 %0, {%1, %1};" : "=l"(r) : "f"(x));
    return r;
}
__device__ __forceinline__ void ffma2(unsigned long long& d,
                                      unsigned long long a,
                                      unsigned long long b) {
    asm("fma.rn.f32x2 %0, %1, %2, %0;" : "+l"(d) : "l"(a), "l"(b));
}
__device__ __forceinline__ float2 unpack2(unsigned long long v) {
    float2 f;
    asm("mov.b64 {%0, %1}, %2;" : "=f"(f.x), "=f"(f.y) : "l"(v));
    return f;
}

// ---------------- prep: fold params (tiny, 1 block) ----------------
__global__ void unit_gcn_prep(const float* __restrict__ pA,
                              const float* __restrict__ pPA1,
                              const float* __restrict__ pPA2,
                              const float* __restrict__ pWc,
                              const float* __restrict__ pbc,
                              const float* __restrict__ pgamma,
                              const float* __restrict__ pbeta,
                              const float* __restrict__ prmean,
                              const float* __restrict__ prvar) {
    int tid = threadIdx.x;
    // Adaptive adjacency, padded rows of 26
    for (int i = tid; i < S_ * V_ * V_; i += blockDim.x) {
        int s = i / (V_ * V_);
        int r = i % (V_ * V_);
        int v = r / V_;
        int w = r % V_;
        g_AeP[(s * V_ + v) * 26 + w] = pA[i] * pPA1[i] + pPA2[i];
    }
    // W transposed/packed: g_Wt[k][o] = Wc[s][o][c], k = s*64 + c
    for (int i = tid; i < K_ * 64; i += blockDim.x) {
        int k = i >> 6, o = i & 63;
        int s = k >> 6, c = k & 63;
        g_Wt[k * 64 + o] = pWc[(s * 64 + o) * 64 + c];
    }
    // BN fold: out = gemm*alpha + bshift (+x, relu). bias folded into bshift.
    if (tid < C_) {
        float sc = pgamma[tid] / sqrtf(prvar[tid] + 1e-5f);
        float btot = pbc[tid] + pbc[64 + tid] + pbc[128 + tid];
        g_alpha[tid] = sc;
        g_bshift[tid] = btot * sc + (pbeta[tid] - prmean[tid] * sc);
    }
}

// ---------------- main fused kernel ----------------
// grid: (75, 64) = (t-tiles, n). block: 256 threads.
// smem: xs[64][4][27] | xa[192*100 + 64] | ae[3*25*26]
#define XS_F  (64 * 4 * 27)            // 6912
#define XA_F  (K_ * COLS + 64)         // 19264
#define AE_F  (S_ * V_ * 26)           // 1950
#define SMEM_FLOATS (XS_F + XA_F + AE_F)
#define SMEM_BYTES  (SMEM_FLOATS * 4)  // 112504

__global__ void __launch_bounds__(NTHREADS, 2)
unit_gcn_main(const float* __restrict__ x, float* __restrict__ out) {
    const int n  = blockIdx.y;
    const int bx = blockIdx.x;       // t-tile
    const int t0 = bx * TT;
    const int tid = threadIdx.x;

    extern __shared__ float sm[];
    float* xs = sm;                  // [c*4+tt][27]
    float* xa = sm + XS_F;           // [k][100]
    float* ae = sm + XS_F + XA_F;    // [s][v][26]

    // Stage adjacency into smem
    for (int i = tid; i < AE_F; i += NTHREADS) ae[i] = g_AeP[i];

    // Stage x tile: per c, floats [t0*25 .. t0*25+100) are contiguous. float4 loads.
    {
        const float4* xp = (const float4*)x;
        for (int q = tid; q < 1600; q += NTHREADS) {
            int c = q / 25;
            int f = q % 25;
            float4 val = xp[(n * 64 + c) * 1875 + bx * 25 + f];
            int p0 = f * 4;
            float vv[4] = {val.x, val.y, val.z, val.w};
#pragma unroll
            for (int j = 0; j < 4; j++) {
                int p = p0 + j;
                int tt = p / 25;
                int w = p - tt * 25;
                xs[(c * 4 + tt) * 27 + w] = vv[j];
            }
        }
    }
    __syncthreads();

    // -------- Step 1: graph aggregation  xa[k][tt*25+w] = sum_v xs[c][tt][v]*Ae[s][v][w]
    // 768 tasks (k,tt), 3 per thread. Ae loads are warp-uniform (broadcast).
#pragma unroll
    for (int r = 0; r < 3; r++) {
        int task = tid + NTHREADS * r;
        int k  = task >> 2;
        int tt = task & 3;
        int s  = k >> 6;
        int c  = k & 63;
        const float* xrow  = xs + (c * 4 + tt) * 27;
        const float* aerow = ae + s * (V_ * 26);

        unsigned long long acc[12];
        float acc24 = 0.0f;
#pragma unroll
        for (int i = 0; i < 12; i++) acc[i] = 0ull;

#pragma unroll
        for (int v = 0; v < V_; v++) {
            float xv = xrow[v];
            unsigned long long xv2 = splat2(xv);
            const float* arow = aerow + v * 26;
#pragma unroll
            for (int i = 0; i < 12; i++) {
                unsigned long long a2 = *(const unsigned long long*)(arow + 2 * i);
                ffma2(acc[i], a2, xv2);
            }
            acc24 = fmaf(xv, arow[24], acc24);
        }
        float* orow = xa + k * COLS + tt * 25;
#pragma unroll
        for (int i = 0; i < 12; i++) {
            float2 f = unpack2(acc[i]);
            orow[2 * i]     = f.x;
            orow[2 * i + 1] = f.y;
        }
        orow[24] = acc24;
    }
    __syncthreads();

    // -------- Step 2: GEMM  y[64][100] = Wt^T[192x64] . xa[192][100]
    // Thread (ty,tx): ty -> 8 output channels (as 4 f32x2 o-pairs), tx -> 4 cols.
    const int ty = tid >> 5;
    const int tx = tid & 31;
    const int o0 = ty * 8;

    unsigned long long acc[4][4];
#pragma unroll
    for (int i = 0; i < 4; i++)
#pragma unroll
        for (int j = 0; j < 4; j++) acc[i][j] = 0ull;

#pragma unroll 4
    for (int k = 0; k < K_; k++) {
        const float* wrow = g_Wt + k * 64 + o0;           // warp-uniform LDG
        unsigned long long w0 = *(const unsigned long long*)(wrow + 0);
        unsigned long long w1 = *(const unsigned long long*)(wrow + 2);
        unsigned long long w2 = *(const unsigned long long*)(wrow + 4);
        unsigned long long w3 = *(const unsigned long long*)(wrow + 6);
        const float* xrow = xa + k * COLS + tx;
        unsigned long long x0 = splat2(xrow[0]);
        unsigned long long x1 = splat2(xrow[32]);
        unsigned long long x2 = splat2(xrow[64]);
        unsigned long long x3 = splat2(xrow[96]);         // may read pad; masked later

        ffma2(acc[0][0], w0, x0); ffma2(acc[0][1], w0, x1);
        ffma2(acc[0][2], w0, x2); ffma2(acc[0][3], w0, x3);
        ffma2(acc[1][0], w1, x0); ffma2(acc[1][1], w1, x1);
        ffma2(acc[1][2], w1, x2); ffma2(acc[1][3], w1, x3);
        ffma2(acc[2][0], w2, x0); ffma2(acc[2][1], w2, x1);
        ffma2(acc[2][2], w2, x2); ffma2(acc[2][3], w2, x3);
        ffma2(acc[3][0], w3, x0); ffma2(acc[3][1], w3, x1);
        ffma2(acc[3][2], w3, x2); ffma2(acc[3][3], w3, x3);
    }

    // -------- Epilogue: BN + bias + residual + relu, store
#pragma unroll
    for (int i = 0; i < 4; i++) {
        int oa = o0 + 2 * i;
        int ob = oa + 1;
        float Aa = g_alpha[oa],  Ab = g_alpha[ob];
        float Ba = g_bshift[oa], Bb = g_bshift[ob];
#pragma unroll
        for (int j = 0; j < 4; j++) {
            int col = tx + 32 * j;
            if (col < COLS) {
                float2 v = unpack2(acc[i][j]);
                int tt = col / 25;
                int w  = col - tt * 25;
                float ra = xs[(oa * 4 + tt) * 27 + w];
                float rb = xs[(ob * 4 + tt) * 27 + w];
                float va = fmaf(v.x, Aa, Ba) + ra;
                float vb = fmaf(v.y, Ab, Bb) + rb;
                va = fmaxf(va, 0.0f);
                vb = fmaxf(vb, 0.0f);
                int base = (n * 64) * 7500 + (t0 + tt) * 25 + w;
                out[base + oa * 7500] = va;
                out[base + ob * 7500] = vb;
            }
        }
    }
}

extern "C" void kernel_launch(void* const* d_in, const int* in_sizes, int n_in,
                              void* d_out, int out_size) {
    const float* x     = (const float*)d_in[0];
    const float* A     = (const float*)d_in[1];
    const float* PA1   = (const float*)d_in[2];
    const float* PA2   = (const float*)d_in[3];
    const float* Wc    = (const float*)d_in[4];
    const float* bc    = (const float*)d_in[5];
    const float* gamma = (const float*)d_in[6];
    const float* beta  = (const float*)d_in[7];
    const float* rmean = (const float*)d_in[8];
    const float* rvar  = (const float*)d_in[9];
    float* out = (float*)d_out;

    unit_gcn_prep<<<1, 256>>>(A, PA1, PA2, Wc, bc, gamma, beta, rmean, rvar);

    cudaFuncSetAttribute(unit_gcn_main,
                         cudaFuncAttributeMaxDynamicSharedMemorySize, SMEM_BYTES);
    dim3 grid(TBLK, N_);
    unit_gcn_main<<<grid, NTHREADS, SMEM_BYTES>>>(x, out);
}

// round 2
// speedup vs baseline: 1.0105x; 1.0105x over previous
#include <cuda_runtime.h>

// Problem dims (fixed by the dataset)
#define N_   64
#define C_   64
#define T_   300
#define V_   25
#define S_   3
#define K_   192            // S_*C_
#define TT   4              // t positions per block
#define COLS 100            // TT*V_
#define TBLK 75             // T_/TT
#define NTHREADS 256

// -------- constant-memory parameter block (written via D2D memcpy) --------
#define AE_OFF  0                    // 3*25*26 = 1950 (pad 26 per row)
#define WT_OFF  1952                 // 192*64 = 12288, [k][o]
#define AL_OFF  (WT_OFF + 12288)     // 64
#define BSH_OFF (AL_OFF + 64)        // 64
#define PAR_F   (BSH_OFF + 64)       // 14432 floats = 57.7KB

__constant__ float c_par[PAR_F];
__device__ __align__(16) float g_stage[PAR_F];

// ---------------- f32x2 helpers (Blackwell packed fp32) ----------------
__device__ __forceinline__ unsigned long long splat2(float x) {
    unsigned long long r;
    asm("mov.b64 %0, {%1, %1};" : "=l"(r) : "f"(x));
    return r;
}
__device__ __forceinline__ void ffma2(unsigned long long& d,
                                      unsigned long long a,
                                      unsigned long long b) {
    asm("fma.rn.f32x2 %0, %1, %2, %0;" : "+l"(d) : "l"(a), "l"(b));
}
__device__ __forceinline__ float2 unpack2(unsigned long long v) {
    float2 f;
    asm("mov.b64 {%0, %1}, %2;" : "=f"(f.x), "=f"(f.y) : "l"(v));
    return f;
}

// ---------------- prep: fold params into staging buffer ----------------
__global__ void unit_gcn_prep(const float* __restrict__ pA,
                              const float* __restrict__ pPA1,
                              const float* __restrict__ pPA2,
                              const float* __restrict__ pWc,
                              const float* __restrict__ pbc,
                              const float* __restrict__ pgamma,
                              const float* __restrict__ pbeta,
                              const float* __restrict__ prmean,
                              const float* __restrict__ prvar) {
    int tid = threadIdx.x;
    // Adaptive adjacency, padded rows of 26
    for (int i = tid; i < S_ * V_ * V_; i += blockDim.x) {
        int s = i / (V_ * V_);
        int r = i % (V_ * V_);
        int v = r / V_;
        int w = r % V_;
        g_stage[AE_OFF + (s * V_ + v) * 26 + w] = pA[i] * pPA1[i] + pPA2[i];
    }
    // W transposed/packed: [k][o] = Wc[s][o][c], k = s*64 + c
    for (int i = tid; i < K_ * 64; i += blockDim.x) {
        int k = i >> 6, o = i & 63;
        int s = k >> 6, c = k & 63;
        g_stage[WT_OFF + k * 64 + o] = pWc[(s * 64 + o) * 64 + c];
    }
    // BN fold: out = gemm*alpha + bshift (+x, relu). Bias folded into bshift.
    if (tid < C_) {
        float sc = pgamma[tid] / sqrtf(prvar[tid] + 1e-5f);
        float btot = pbc[tid] + pbc[64 + tid] + pbc[128 + tid];
        g_stage[AL_OFF + tid] = sc;
        g_stage[BSH_OFF + tid] = btot * sc + (pbeta[tid] - prmean[tid] * sc);
    }
}

// ---------------- main fused kernel ----------------
// grid: (75, 64) = (t-tiles, n). block: 256 threads.
// smem: xs[64][4][27] | xa[192*100 + 64]
#define XS_F  (64 * 4 * 27)            // 6912
#define XA_F  (K_ * COLS + 64)         // 19264
#define SMEM_FLOATS (XS_F + XA_F)
#define SMEM_BYTES  (SMEM_FLOATS * 4)  // 104704

__global__ void __launch_bounds__(NTHREADS, 2)
unit_gcn_main(const float* __restrict__ x, float* __restrict__ out) {
    const int n  = blockIdx.y;
    const int bx = blockIdx.x;       // t-tile
    const int t0 = bx * TT;
    const int tid = threadIdx.x;

    extern __shared__ float sm[];
    float* xs = sm;                  // [c*4+tt][27]
    float* xa = sm + XS_F;           // [k][100]

    // Stage x tile: per c, floats [t0*25 .. t0*25+100) are contiguous. float4 loads.
    {
        const float4* xp = (const float4*)x;
        for (int q = tid; q < 1600; q += NTHREADS) {
            int c = q / 25;
            int f = q % 25;
            float4 val = xp[(n * 64 + c) * 1875 + bx * 25 + f];
            int p0 = f * 4;
            float vv[4] = {val.x, val.y, val.z, val.w};
#pragma unroll
            for (int j = 0; j < 4; j++) {
                int p = p0 + j;
                int tt = p / 25;
                int w = p - tt * 25;
                xs[(c * 4 + tt) * 27 + w] = vv[j];
            }
        }
    }
    __syncthreads();

    // -------- Step 1: graph aggregation
    // xa[k][tt*25+w] = sum_v xs[c][tt][v] * Ae[s][v][w]; s = r, k = s*64 + c.
    // A-row reads are warp-uniform constant loads (LDCU) -> off the L1/LSU path.
#pragma unroll
    for (int r = 0; r < 3; r++) {
        int task = tid + NTHREADS * r;
        int k  = task >> 2;              // s*64 + c; s == r
        int tt = task & 3;
        int c  = k & 63;
        const float* xrow = xs + (c * 4 + tt) * 27;

        // hoist x row into registers (25 independent LDS, MLP)
        float xv[V_];
#pragma unroll
        for (int v = 0; v < V_; v++) xv[v] = xrow[v];

        const float* aerow = c_par + AE_OFF + r * (V_ * 26);

        unsigned long long acc[12];
        float acc24 = 0.0f;
#pragma unroll
        for (int i = 0; i < 12; i++) acc[i] = 0ull;

#pragma unroll 5
        for (int v = 0; v < V_; v++) {
            unsigned long long xv2 = splat2(xv[v]);
            const float* arow = aerow + v * 26;
#pragma unroll
            for (int i = 0; i < 12; i++) {
                unsigned long long a2 = *(const unsigned long long*)(arow + 2 * i);
                ffma2(acc[i], a2, xv2);
            }
            acc24 = fmaf(xv[v], arow[24], acc24);
        }
        float* orow = xa + k * COLS + tt * 25;
#pragma unroll
        for (int i = 0; i < 12; i++) {
            float2 f = unpack2(acc[i]);
            orow[2 * i]     = f.x;
            orow[2 * i + 1] = f.y;
        }
        orow[24] = acc24;
    }
    __syncthreads();

    // -------- Step 2: GEMM  y[64][100] = Wt^T[192x64] . xa[192][100]
    // Thread (ty,tx): ty -> 8 output channels (4 f32x2 o-pairs),
    // tx -> column quad [4tx, 4tx+3] via ONE LDS.128 per k. Lanes tx>=25 idle.
    const int ty = tid >> 5;
    const int tx = tid & 31;
    const int o0 = ty * 8;

    unsigned long long acc[4][4];
#pragma unroll
    for (int i = 0; i < 4; i++)
#pragma unroll
        for (int j = 0; j < 4; j++) acc[i][j] = 0ull;

    const float* wbase = c_par + WT_OFF + o0;
    const float* xbase = xa + tx * 4;

#pragma unroll 4
    for (int k = 0; k < K_; k++) {
        const float* wrow = wbase + k * 64;      // warp-uniform LDCU.64 x4
        unsigned long long w0 = *(const unsigned long long*)(wrow + 0);
        unsigned long long w1 = *(const unsigned long long*)(wrow + 2);
        unsigned long long w2 = *(const unsigned long long*)(wrow + 4);
        unsigned long long w3 = *(const unsigned long long*)(wrow + 6);
        float4 xq = *(const float4*)(xbase + k * COLS);   // LDS.128
        unsigned long long x0 = splat2(xq.x);
        unsigned long long x1 = splat2(xq.y);
        unsigned long long x2 = splat2(xq.z);
        unsigned long long x3 = splat2(xq.w);

        ffma2(acc[0][0], w0, x0); ffma2(acc[0][1], w0, x1);
        ffma2(acc[0][2], w0, x2); ffma2(acc[0][3], w0, x3);
        ffma2(acc[1][0], w1, x0); ffma2(acc[1][1], w1, x1);
        ffma2(acc[1][2], w1, x2); ffma2(acc[1][3], w1, x3);
        ffma2(acc[2][0], w2, x0); ffma2(acc[2][1], w2, x1);
        ffma2(acc[2][2], w2, x2); ffma2(acc[2][3], w2, x3);
        ffma2(acc[3][0], w3, x0); ffma2(acc[3][1], w3, x1);
        ffma2(acc[3][2], w3, x2); ffma2(acc[3][3], w3, x3);
    }

    // -------- Epilogue: BN + bias + residual + relu, store
    if (tx < 25) {
#pragma unroll
        for (int i = 0; i < 4; i++) {
            int oa = o0 + 2 * i;
            int ob = oa + 1;
            float Aa = c_par[AL_OFF + oa],  Ab = c_par[AL_OFF + ob];
            float Ba = c_par[BSH_OFF + oa], Bb = c_par[BSH_OFF + ob];
#pragma unroll
            for (int j = 0; j < 4; j++) {
                int col = tx * 4 + j;            // < 100 guaranteed (tx<25)
                float2 v = unpack2(acc[i][j]);
                int tt = col / 25;
                int w  = col - tt * 25;
                float ra = xs[(oa * 4 + tt) * 27 + w];
                float rb = xs[(ob * 4 + tt) * 27 + w];
                float va = fmaf(v.x, Aa, Ba) + ra;
                float vb = fmaf(v.y, Ab, Bb) + rb;
                va = fmaxf(va, 0.0f);
                vb = fmaxf(vb, 0.0f);
                int base = (n * 64) * 7500 + (t0 + tt) * 25 + w;
                out[base + oa * 7500] = va;
                out[base + ob * 7500] = vb;
            }
        }
    }
}

extern "C" void kernel_launch(void* const* d_in, const int* in_sizes, int n_in,
                              void* d_out, int out_size) {
    const float* x     = (const float*)d_in[0];
    const float* A     = (const float*)d_in[1];
    const float* PA1   = (const float*)d_in[2];
    const float* PA2   = (const float*)d_in[3];
    const float* Wc    = (const float*)d_in[4];
    const float* bc    = (const float*)d_in[5];
    const float* gamma = (const float*)d_in[6];
    const float* beta  = (const float*)d_in[7];
    const float* rmean = (const float*)d_in[8];
    const float* rvar  = (const float*)d_in[9];
    float* out = (float*)d_out;

    unit_gcn_prep<<<1, 256>>>(A, PA1, PA2, Wc, bc, gamma, beta, rmean, rvar);

    // Push folded params into the constant bank (D2D, graph-capturable).
    void* src = nullptr;
    cudaGetSymbolAddress(&src, g_stage);
    cudaMemcpyToSymbolAsync(c_par, src, PAR_F * sizeof(float), 0,
                            cudaMemcpyDeviceToDevice, 0);

    cudaFuncSetAttribute(unit_gcn_main,
                         cudaFuncAttributeMaxDynamicSharedMemorySize, SMEM_BYTES);
    dim3 grid(TBLK, N_);
    unit_gcn_main<<<grid, NTHREADS, SMEM_BYTES>>>(x, out);
}

// round 3
// speedup vs baseline: 1.2311x; 1.2183x over previous
#include <cuda_runtime.h>

// Problem dims (fixed by the dataset)
#define N_   64
#define C_   64
#define T_   300
#define V_   25
#define S_   3
#define TT   4              // t positions per block
#define COLS 100            // TT*V_
#define TBLK 75             // T_/TT
#define NTHREADS 256

// -------- global folded parameters (written by prep kernel) --------
__device__ __align__(16) float g_Ae[S_ * V_ * 28];   // [s][v][28] padded
__device__ __align__(16) float g_Wt[S_ * 64 * 64];   // [s][k][o]
__device__ __align__(16) float g_ab[128];            // [0..63]=alpha, [64..127]=bshift

// ---------------- f32x2 helpers (Blackwell packed fp32) ----------------
__device__ __forceinline__ unsigned long long splat2(float x) {
    unsigned long long r;
    asm("mov.b64 %0, {%1, %1};" : "=l"(r) : "f"(x));
    return r;
}
__device__ __forceinline__ void ffma2(unsigned long long& d,
                                      unsigned long long a,
                                      unsigned long long b) {
    asm("fma.rn.f32x2 %0, %1, %2, %0;" : "+l"(d) : "l"(a), "l"(b));
}
__device__ __forceinline__ float2 unpack2(unsigned long long v) {
    float2 f;
    asm("mov.b64 {%0, %1}, %2;" : "=f"(f.x), "=f"(f.y) : "l"(v));
    return f;
}

// ---------------- prep: fold params (tiny, 1 block) ----------------
__global__ void unit_gcn_prep(const float* __restrict__ pA,
                              const float* __restrict__ pPA1,
                              const float* __restrict__ pPA2,
                              const float* __restrict__ pWc,
                              const float* __restrict__ pbc,
                              const float* __restrict__ pgamma,
                              const float* __restrict__ pbeta,
                              const float* __restrict__ prmean,
                              const float* __restrict__ prvar) {
    int tid = threadIdx.x;
    // Adaptive adjacency, rows padded to 28 (pad zeroed)
    for (int i = tid; i < S_ * V_ * 28; i += blockDim.x) {
        int sv = i / 28;
        int w = i % 28;
        g_Ae[i] = (w < V_)
            ? pA[sv * V_ + w] * pPA1[sv * V_ + w] + pPA2[sv * V_ + w]
            : 0.0f;
    }
    // W packed per subset: g_Wt[s][k][o] = Wc[s][o][k]
    for (int i = tid; i < S_ * 64 * 64; i += blockDim.x) {
        int s = i >> 12;
        int k = (i >> 6) & 63;
        int o = i & 63;
        g_Wt[i] = pWc[(s * 64 + o) * 64 + k];
    }
    // BN fold: out = gemm*alpha + bshift (+x, relu). Bias folded into bshift.
    if (tid < C_) {
        float sc = pgamma[tid] / sqrtf(prvar[tid] + 1e-5f);
        float btot = pbc[tid] + pbc[64 + tid] + pbc[128 + tid];
        g_ab[tid] = sc;
        g_ab[64 + tid] = btot * sc + (pbeta[tid] - prmean[tid] * sc);
    }
}

// ---------------- main fused kernel ----------------
// grid: (75, 64) = (t-tiles, n). block: 256 threads. smem 78KB -> 2 CTAs/SM.
#define AE_F  (S_ * V_ * 28)           // 2100
#define W_F   (64 * 64)                // 4096 (one subset)
#define XA_F  (64 * COLS + 32)         // 6432 (pad for tail reads)
#define XS_F  (64 * 4 * 27)            // 6912
#define SMEM_FLOATS (AE_F + W_F + XA_F + XS_F)
#define SMEM_BYTES  (SMEM_FLOATS * 4)  // 78160

__global__ void __launch_bounds__(NTHREADS, 2)
unit_gcn_main(const float* __restrict__ x, float* __restrict__ out) {
    const int n  = blockIdx.y;
    const int bx = blockIdx.x;       // t-tile
    const int t0 = bx * TT;
    const int tid = threadIdx.x;

    extern __shared__ float sm[];
    float* ae  = sm;                         // [s][v][28]
    float* wsm = sm + AE_F;                  // [k][64] (current subset)
    float* xa  = sm + AE_F + W_F;            // [c][100]
    float* xs  = sm + AE_F + W_F + XA_F;     // [(c*4+tt)][27]

    // Stage adjacency (float4)
    {
        const float4* src = (const float4*)g_Ae;
        float4* dst = (float4*)ae;
        for (int i = tid; i < AE_F / 4; i += NTHREADS) dst[i] = src[i];
    }

    // Stage x tile: per c, floats [t0*25 .. t0*25+100) contiguous. float4 loads.
    {
        const float4* xp = (const float4*)x;
        for (int q = tid; q < 1600; q += NTHREADS) {
            int c = q / 25;
            int f = q % 25;
            float4 val = xp[(n * 64 + c) * 1875 + bx * 25 + f];
            int p0 = f * 4;
            float vv[4] = {val.x, val.y, val.z, val.w};
#pragma unroll
            for (int j = 0; j < 4; j++) {
                int p = p0 + j;
                int tt = p / 25;
                int w = p - tt * 25;
                xs[(c * 4 + tt) * 27 + w] = vv[j];
            }
        }
    }
    __syncthreads();

    // Per-thread GEMM coords: ty -> 8 output channels, tx -> col quad [4tx..4tx+3]
    const int ty = tid >> 5;
    const int tx = tid & 31;
    const int o0 = ty * 8;

    unsigned long long acc[4][4];
#pragma unroll
    for (int i = 0; i < 4; i++)
#pragma unroll
        for (int j = 0; j < 4; j++) acc[i][j] = 0ull;

    // Step-1 task for this thread: one (c, tt) per subset
    const int c1  = tid >> 2;
    const int tt1 = tid & 3;
    const float* xrow = xs + (c1 * 4 + tt1) * 27;
    float* orow = xa + c1 * COLS + tt1 * 25;

#pragma unroll
    for (int s = 0; s < S_; s++) {
        // ---- stage W_s into smem (coalesced float4) ----
        {
            const float4* src = (const float4*)(g_Wt + s * W_F);
            float4* dst = (float4*)wsm;
#pragma unroll
            for (int j = 0; j < 4; j++) dst[tid + NTHREADS * j] = src[tid + NTHREADS * j];
        }

        // ---- graph aggregation: xa[c][tt*25+w] = sum_v xs[c][tt][v]*Ae[s][v][w]
        {
            const float* aerow = ae + s * (V_ * 28);
            unsigned long long a1[12];
            float a24 = 0.0f;
#pragma unroll
            for (int i = 0; i < 12; i++) a1[i] = 0ull;

#pragma unroll
            for (int v = 0; v < V_; v++) {
                float xv = xrow[v];
                unsigned long long xv2 = splat2(xv);
                const ulonglong2* ar = (const ulonglong2*)(aerow + v * 28);
                ulonglong2 q0 = ar[0], q1 = ar[1], q2 = ar[2];   // cols 0..23
                ffma2(a1[0], q0.x, xv2); ffma2(a1[1], q0.y, xv2);
                ffma2(a1[2], q1.x, xv2); ffma2(a1[3], q1.y, xv2);
                ffma2(a1[4], q2.x, xv2); ffma2(a1[5], q2.y, xv2);
                const ulonglong2* ar2 = ar + 3;                  // cols 12..23? no:
                ulonglong2 q3 = ar2[0], q4 = ar2[1], q5 = ar2[2];
                // NOTE: ar[0..2] = cols 0..11, ar2[0..2] = cols 12..23
                ffma2(a1[6], q3.x, xv2); ffma2(a1[7], q3.y, xv2);
                ffma2(a1[8], q4.x, xv2); ffma2(a1[9], q4.y, xv2);
                ffma2(a1[10], q5.x, xv2); ffma2(a1[11], q5.y, xv2);
                a24 = fmaf(xv, aerow[v * 28 + 24], a24);
            }
            // Fix pairing: a1[i] accumulated cols 2i..2i+1 in order q0..q5 = cols 0..23
#pragma unroll
            for (int i = 0; i < 12; i++) {
                float2 f = unpack2(a1[i]);
                orow[2 * i]     = f.x;
                orow[2 * i + 1] = f.y;
            }
            orow[24] = a24;
        }
        __syncthreads();   // xa + W_s ready

        // ---- GEMM accumulate: acc += Wt_s[k][o0..o0+7] * xa[k][4tx..4tx+3]
        const float* wbase = wsm + o0;
        const float* xbase = xa + tx * 4;
#pragma unroll 4
        for (int k = 0; k < 64; k++) {
            const float* wrow = wbase + k * 64;
            ulonglong2 wA = *(const ulonglong2*)(wrow);       // o0..o0+3
            ulonglong2 wB = *(const ulonglong2*)(wrow + 4);   // o0+4..o0+7
            float4 xq = *(const float4*)(xbase + k * COLS);
            unsigned long long x0 = splat2(xq.x);
            unsigned long long x1 = splat2(xq.y);
            unsigned long long x2 = splat2(xq.z);
            unsigned long long x3 = splat2(xq.w);

            ffma2(acc[0][0], wA.x, x0); ffma2(acc[0][1], wA.x, x1);
            ffma2(acc[0][2], wA.x, x2); ffma2(acc[0][3], wA.x, x3);
            ffma2(acc[1][0], wA.y, x0); ffma2(acc[1][1], wA.y, x1);
            ffma2(acc[1][2], wA.y, x2); ffma2(acc[1][3], wA.y, x3);
            ffma2(acc[2][0], wB.x, x0); ffma2(acc[2][1], wB.x, x1);
            ffma2(acc[2][2], wB.x, x2); ffma2(acc[2][3], wB.x, x3);
            ffma2(acc[3][0], wB.y, x0); ffma2(acc[3][1], wB.y, x1);
            ffma2(acc[3][2], wB.y, x2); ffma2(acc[3][3], wB.y, x3);
        }
        if (s < S_ - 1) __syncthreads();   // before next s overwrites xa/W
    }

    // -------- Epilogue: BN + bias + residual + relu, store
    if (tx < 25) {
#pragma unroll
        for (int i = 0; i < 4; i++) {
            int oa = o0 + 2 * i;
            int ob = oa + 1;
            float2 Al = *(const float2*)(g_ab + oa);        // warp-uniform LDG
            float2 Bs = *(const float2*)(g_ab + 64 + oa);
#pragma unroll
            for (int j = 0; j < 4; j++) {
                int col = tx * 4 + j;            // < 100 guaranteed (tx<25)
                float2 v = unpack2(acc[i][j]);
                int tt = col / 25;
                int w  = col - tt * 25;
                float ra = xs[(oa * 4 + tt) * 27 + w];
                float rb = xs[(ob * 4 + tt) * 27 + w];
                float va = fmaf(v.x, Al.x, Bs.x) + ra;
                float vb = fmaf(v.y, Al.y, Bs.y) + rb;
                va = fmaxf(va, 0.0f);
                vb = fmaxf(vb, 0.0f);
                int base = (n * 64) * 7500 + (t0 + tt) * 25 + w;
                out[base + oa * 7500] = va;
                out[base + ob * 7500] = vb;
            }
        }
    }
}

extern "C" void kernel_launch(void* const* d_in, const int* in_sizes, int n_in,
                              void* d_out, int out_size) {
    const float* x     = (const float*)d_in[0];
    const float* A     = (const float*)d_in[1];
    const float* PA1   = (const float*)d_in[2];
    const float* PA2   = (const float*)d_in[3];
    const float* Wc    = (const float*)d_in[4];
    const float* bc    = (const float*)d_in[5];
    const float* gamma = (const float*)d_in[6];
    const float* beta  = (const float*)d_in[7];
    const float* rmean = (const float*)d_in[8];
    const float* rvar  = (const float*)d_in[9];
    float* out = (float*)d_out;

    unit_gcn_prep<<<1, 256>>>(A, PA1, PA2, Wc, bc, gamma, beta, rmean, rvar);

    cudaFuncSetAttribute(unit_gcn_main,
                         cudaFuncAttributeMaxDynamicSharedMemorySize, SMEM_BYTES);
    dim3 grid(TBLK, N_);
    unit_gcn_main<<<grid, NTHREADS, SMEM_BYTES>>>(x, out);
}

// round 5
// speedup vs baseline: 2.0591x; 1.6725x over previous
#include <cuda_runtime.h>
#include <cuda_bf16.h>
#include <cstdint>

// Problem dims (fixed by the dataset)
#define N_   64
#define C_   64
#define T_   300
#define V_   25
#define S_   3
#define TT   4              // t positions per block
#define COLS 100            // TT*V_
#define TBLK 75             // T_/TT
#define NTHREADS 256

// -------- global folded parameters (written by prep kernel) --------
__device__ __align__(16) float g_Ae[S_ * V_ * 28];    // [s][v][28]
__device__ __align__(16) uint4 g_Wf[S_ * 4 * 8 * 32]; // W frags [s][kt][ntg][lane]
__device__ __align__(16) float g_ab[128];             // alpha | bshift

// ---------------- f32x2 helpers (Blackwell packed fp32) ----------------
__device__ __forceinline__ unsigned long long splat2(float x) {
    unsigned long long r;
    asm("mov.b64 %0, {%1, %1};" : "=l"(r) : "f"(x));
    return r;
}
__device__ __forceinline__ void ffma2(unsigned long long& d,
                                      unsigned long long a,
                                      unsigned long long b) {
    asm("fma.rn.f32x2 %0, %1, %2, %0;" : "+l"(d) : "l"(a), "l"(b));
}
__device__ __forceinline__ float2 unpack2(unsigned long long v) {
    float2 f;
    asm("mov.b64 {%0, %1}, %2;" : "=f"(f.x), "=f"(f.y) : "l"(v));
    return f;
}

// ---------------- bf16 / mma helpers ----------------
// packbf(hi_elem, lo_elem): low 16 bits = bf16(lo_elem)
__device__ __forceinline__ uint32_t packbf(float hi, float lo) {
    uint32_t d;
    asm("cvt.rn.bf16x2.f32 %0, %1, %2;" : "=r"(d) : "f"(hi), "f"(lo));
    return d;
}
__device__ __forceinline__ void mma16816(float* c, const uint32_t* a,
                                         uint32_t b0, uint32_t b1) {
    asm volatile(
        "mma.sync.aligned.m16n8k16.row.col.f32.bf16.bf16.f32 "
        "{%0,%1,%2,%3}, {%4,%5,%6,%7}, {%8,%9}, {%0,%1,%2,%3};"
        : "+f"(c[0]), "+f"(c[1]), "+f"(c[2]), "+f"(c[3])
        : "r"(a[0]), "r"(a[1]), "r"(a[2]), "r"(a[3]), "r"(b0), "r"(b1));
}

// ---------------- prep: fold params (tiny, few blocks) ----------------
__global__ void unit_gcn_prep(const float* __restrict__ pA,
                              const float* __restrict__ pPA1,
                              const float* __restrict__ pPA2,
                              const float* __restrict__ pWc,
                              const float* __restrict__ pbc,
                              const float* __restrict__ pgamma,
                              const float* __restrict__ pbeta,
                              const float* __restrict__ prmean,
                              const float* __restrict__ prvar) {
    int tid = blockIdx.x * blockDim.x + threadIdx.x;
    // Adaptive adjacency, rows padded to 28 (pad zeroed)
    for (int i = tid; i < S_ * V_ * 28; i += blockDim.x * gridDim.x) {
        int sv = i / 28;
        int w = i % 28;
        g_Ae[i] = (w < V_)
            ? pA[sv * V_ + w] * pPA1[sv * V_ + w] + pPA2[sv * V_ + w]
            : 0.0f;
    }
    // W fragments for mma.m16n8k16 B operand (col-major KxN), hi/lo bf16.
    // idx: [s][kt][ntg][lane]; per lane: n = ntg*8 + lane/4, k0 = kt*16 + (lane%4)*2
    for (int i = tid; i < S_ * 4 * 8 * 32; i += blockDim.x * gridDim.x) {
        int lane = i & 31;
        int ntg  = (i >> 5) & 7;
        int kt   = (i >> 8) & 3;
        int s    = i >> 10;
        int n  = ntg * 8 + (lane >> 2);
        int k0 = kt * 16 + (lane & 3) * 2;
        const float* wr = pWc + (s * 64 + n) * 64;
        float w0 = wr[k0], w1 = wr[k0 + 1], w8 = wr[k0 + 8], w9 = wr[k0 + 9];
        uint32_t h01 = packbf(w1, w0);
        uint32_t h89 = packbf(w9, w8);
        float r0 = w0 - __uint_as_float(h01 << 16);
        float r1 = w1 - __uint_as_float(h01 & 0xffff0000u);
        float r8 = w8 - __uint_as_float(h89 << 16);
        float r9 = w9 - __uint_as_float(h89 & 0xffff0000u);
        uint4 frag;
        frag.x = h01;
        frag.y = h89;
        frag.z = packbf(r1, r0);
        frag.w = packbf(r9, r8);
        g_Wf[i] = frag;
    }
    // BN fold: out = gemm*alpha + bshift (+x, relu). Bias folded into bshift.
    if (tid < C_) {
        float sc = pgamma[tid] / sqrtf(prvar[tid] + 1e-5f);
        float btot = pbc[tid] + pbc[64 + tid] + pbc[128 + tid];
        g_ab[tid] = sc;
        g_ab[64 + tid] = btot * sc + (pbeta[tid] - prmean[tid] * sc);
    }
}

// ---------------- main fused kernel ----------------
// grid: (75, 64). block 256. smem ~61KB -> 2 CTAs/SM.
#define AB_F  128
#define XA_F  (64 * COLS + 128)       // 6528 (pad: frag reads at m<128 stay in-bounds)
#define XS_F  (64 * 4 * 27)           // 6912
#define AE_F  (S_ * V_ * 28)          // 2100
#define SMEM_FLOATS (AB_F + XA_F + XS_F + AE_F)
#define SMEM_BYTES  (SMEM_FLOATS * 4) // 62672

__global__ void __launch_bounds__(NTHREADS, 2)
unit_gcn_main(const float* __restrict__ x, float* __restrict__ out) {
    const int n  = blockIdx.y;
    const int bx = blockIdx.x;       // t-tile
    const int t0 = bx * TT;
    const int tid = threadIdx.x;
    const int wid = tid >> 5;
    const int lane = tid & 31;

    extern __shared__ float sm[];
    float* ab = sm;                  // alpha[64] | bshift[64]
    float* xa = sm + AB_F;           // [k=c][m=col], stride 100
    float* xs = sm + AB_F + XA_F;    // [(c*4+tt)][27]
    float* ae = sm + AB_F + XA_F + XS_F;   // [s][v][28]

    // Stage BN constants + adjacency
    if (tid < 128) ab[tid] = g_ab[tid];
    {
        const float4* src = (const float4*)g_Ae;
        float4* dst = (float4*)ae;
        for (int i = tid; i < AE_F / 4; i += NTHREADS) dst[i] = src[i];
    }

    // Stage x tile: per c, floats [t0*25 .. t0*25+100) contiguous. float4 loads.
    {
        const float4* xp = (const float4*)x;
        for (int q = tid; q < 1600; q += NTHREADS) {
            int c = q / 25;
            int f = q % 25;
            float4 val = xp[(n * 64 + c) * 1875 + bx * 25 + f];
            int p0 = f * 4;
            float vv[4] = {val.x, val.y, val.z, val.w};
#pragma unroll
            for (int j = 0; j < 4; j++) {
                int p = p0 + j;
                int tt = p / 25;
                int w = p - tt * 25;
                xs[(c * 4 + tt) * 27 + w] = vv[j];
            }
        }
    }
    __syncthreads();

    // GEMM warp coords: wy (0..3) -> m rows [wy*32, wy*32+32); wx (0..1) -> n [wx*32,+32)
    const int wy = wid & 3;
    const int wx = wid >> 2;

    float acc[2][4][4];
#pragma unroll
    for (int i = 0; i < 2; i++)
#pragma unroll
        for (int j = 0; j < 4; j++)
#pragma unroll
            for (int q = 0; q < 4; q++) acc[i][j][q] = 0.0f;

    // Step-1 task for this thread: (c1 = k-row, tt1)
    const int c1  = tid >> 2;
    const int tt1 = tid & 3;
    const float* xrow = xs + (c1 * 4 + tt1) * 27;
    float* orow = xa + c1 * COLS + tt1 * 25;

#pragma unroll
    for (int s = 0; s < S_; s++) {
        // ---- Step 1: graph aggregation (FFMA2), xa[c1][tt1*25+w] ----
        {
            const float* aerow = ae + s * (V_ * 28);
            unsigned long long a1[12];
            float a24 = 0.0f;
#pragma unroll
            for (int i = 0; i < 12; i++) a1[i] = 0ull;

#pragma unroll
            for (int v = 0; v < V_; v++) {
                float xv = xrow[v];
                unsigned long long xv2 = splat2(xv);
                const ulonglong2* ar = (const ulonglong2*)(aerow + v * 28);
                ulonglong2 q0 = ar[0], q1 = ar[1], q2 = ar[2];
                ulonglong2 q3 = ar[3], q4 = ar[4], q5 = ar[5];
                ffma2(a1[0], q0.x, xv2);  ffma2(a1[1], q0.y, xv2);
                ffma2(a1[2], q1.x, xv2);  ffma2(a1[3], q1.y, xv2);
                ffma2(a1[4], q2.x, xv2);  ffma2(a1[5], q2.y, xv2);
                ffma2(a1[6], q3.x, xv2);  ffma2(a1[7], q3.y, xv2);
                ffma2(a1[8], q4.x, xv2);  ffma2(a1[9], q4.y, xv2);
                ffma2(a1[10], q5.x, xv2); ffma2(a1[11], q5.y, xv2);
                a24 = fmaf(xv, aerow[v * 28 + 24], a24);
            }
#pragma unroll
            for (int i = 0; i < 12; i++) {
                float2 f = unpack2(a1[i]);
                orow[2 * i]     = f.x;
                orow[2 * i + 1] = f.y;
            }
            orow[24] = a24;
        }
        __syncthreads();   // xa(s) visible

        // ---- Step 2: HMMA GEMM, D[m,n] += xa^T[m,k] * W[k,n], K=64 ----
        {
            const uint4* wfs = g_Wf + (s * 4) * 8 * 32 + lane;
#pragma unroll
            for (int kt = 0; kt < 4; kt++) {
                uint4 Bf[4];
#pragma unroll
                for (int j = 0; j < 4; j++)
                    Bf[j] = __ldg(wfs + (kt * 8 + wx * 4 + j) * 32);

                const int k0 = kt * 16 + (lane & 3) * 2;
#pragma unroll
                for (int mti = 0; mti < 2; mti++) {
                    const int m = (wy * 2 + mti) * 16 + (lane >> 2);
                    const float* xk = xa + k0 * COLS + m;
                    float x00 = xk[0];
                    float x01 = xk[COLS];
                    float x10 = xk[8];
                    float x11 = xk[COLS + 8];
                    float x20 = xk[8 * COLS];
                    float x21 = xk[9 * COLS];
                    float x30 = xk[8 * COLS + 8];
                    float x31 = xk[9 * COLS + 8];

                    uint32_t ah[4], al[4];
                    ah[0] = packbf(x01, x00);
                    ah[1] = packbf(x11, x10);
                    ah[2] = packbf(x21, x20);
                    ah[3] = packbf(x31, x30);
                    {
                        float r0 = x00 - __uint_as_float(ah[0] << 16);
                        float r1 = x01 - __uint_as_float(ah[0] & 0xffff0000u);
                        al[0] = packbf(r1, r0);
                        r0 = x10 - __uint_as_float(ah[1] << 16);
                        r1 = x11 - __uint_as_float(ah[1] & 0xffff0000u);
                        al[1] = packbf(r1, r0);
                        r0 = x20 - __uint_as_float(ah[2] << 16);
                        r1 = x21 - __uint_as_float(ah[2] & 0xffff0000u);
                        al[2] = packbf(r1, r0);
                        r0 = x30 - __uint_as_float(ah[3] << 16);
                        r1 = x31 - __uint_as_float(ah[3] & 0xffff0000u);
                        al[3] = packbf(r1, r0);
                    }
#pragma unroll
                    for (int j = 0; j < 4; j++) {
                        mma16816(acc[mti][j], ah, Bf[j].x, Bf[j].y);  // Ah*Bh
                        mma16816(acc[mti][j], al, Bf[j].x, Bf[j].y);  // Al*Bh
                        mma16816(acc[mti][j], ah, Bf[j].z, Bf[j].w);  // Ah*Bl
                    }
                }
            }
        }
        if (s < S_ - 1) __syncthreads();   // before next s overwrites xa
    }

    // -------- Epilogue: BN + residual + relu, store --------
    // Preload this thread's 8 (alpha, bshift) pairs
    const int nb = wx * 32 + (lane & 3) * 2;
    float alv[8], bsv[8];
#pragma unroll
    for (int j = 0; j < 4; j++) {
        alv[2 * j]     = ab[nb + j * 8];
        alv[2 * j + 1] = ab[nb + j * 8 + 1];
        bsv[2 * j]     = ab[64 + nb + j * 8];
        bsv[2 * j + 1] = ab[64 + nb + j * 8 + 1];
    }

#pragma unroll
    for (int mti = 0; mti < 2; mti++) {
#pragma unroll
        for (int half = 0; half < 2; half++) {
            int m = (wy * 2 + mti) * 16 + (lane >> 2) + half * 8;
            if (m < COLS) {
                int tt = m / 25;
                int w  = m - tt * 25;
                int base = n * 480000 + (t0 + tt) * 25 + w;
                const float* xsr = xs + tt * 27 + w;
#pragma unroll
                for (int j = 0; j < 4; j++) {
                    int o0 = nb + j * 8;
                    float c0 = acc[mti][j][half * 2];
                    float c1 = acc[mti][j][half * 2 + 1];
                    float r0 = xsr[o0 * 108];          // xs[(o0*4+tt)*27+w]
                    float r1 = xsr[(o0 + 1) * 108];
                    float y0 = fmaf(c0, alv[2 * j], bsv[2 * j]) + r0;
                    float y1 = fmaf(c1, alv[2 * j + 1], bsv[2 * j + 1]) + r1;
                    out[base + o0 * 7500]       = fmaxf(y0, 0.0f);
                    out[base + (o0 + 1) * 7500] = fmaxf(y1, 0.0f);
                }
            }
        }
    }
}

extern "C" void kernel_launch(void* const* d_in, const int* in_sizes, int n_in,
                              void* d_out, int out_size) {
    const float* x     = (const float*)d_in[0];
    const float* A     = (const float*)d_in[1];
    const float* PA1   = (const float*)d_in[2];
    const float* PA2   = (const float*)d_in[3];
    const float* Wc    = (const float*)d_in[4];
    const float* bc    = (const float*)d_in[5];
    const float* gamma = (const float*)d_in[6];
    const float* beta  = (const float*)d_in[7];
    const float* rmean = (const float*)d_in[8];
    const float* rvar  = (const float*)d_in[9];
    float* out = (float*)d_out;

    unit_gcn_prep<<<8, 256>>>(A, PA1, PA2, Wc, bc, gamma, beta, rmean, rvar);

    cudaFuncSetAttribute(unit_gcn_main,
                         cudaFuncAttributeMaxDynamicSharedMemorySize, SMEM_BYTES);
    dim3 grid(TBLK, N_);
    unit_gcn_main<<<grid, NTHREADS, SMEM_BYTES>>>(x, out);
}

// round 6
// speedup vs baseline: 2.5300x; 1.2287x over previous
#include <cuda_runtime.h>
#include <cuda_bf16.h>
#include <cstdint>

// Problem dims (fixed by the dataset)
#define N_   64
#define C_   64
#define T_   300
#define V_   25
#define S_   3
#define TT   4              // t positions per block
#define COLS 100            // TT*V_
#define TBLK 75             // T_/TT
#define NTHREADS 256

// -------- global folded parameters (written by prep kernel) --------
__device__ __align__(16) uint4 g_Wf[S_ * 4 * 8 * 32];   // W frags [s][kt][ntg][lane]
__device__ __align__(16) uint4 g_Af[S_ * 2 * 2 * 2 * 32]; // Ae^T frags [s][mt][kt][hl][lane]
__device__ __align__(16) float g_ab[128];                // alpha | bshift

// ---------------- bf16 / mma helpers ----------------
// packbf(hi_elem, lo_elem): low 16 bits = bf16(lo_elem)  (convention verified R5)
__device__ __forceinline__ uint32_t packbf(float hi, float lo) {
    uint32_t d;
    asm("cvt.rn.bf16x2.f32 %0, %1, %2;" : "=r"(d) : "f"(hi), "f"(lo));
    return d;
}
__device__ __forceinline__ void mma16816(float* c, const uint32_t* a,
                                         uint32_t b0, uint32_t b1) {
    asm volatile(
        "mma.sync.aligned.m16n8k16.row.col.f32.bf16.bf16.f32 "
        "{%0,%1,%2,%3}, {%4,%5,%6,%7}, {%8,%9}, {%0,%1,%2,%3};"
        : "+f"(c[0]), "+f"(c[1]), "+f"(c[2]), "+f"(c[3])
        : "r"(a[0]), "r"(a[1]), "r"(a[2]), "r"(a[3]), "r"(b0), "r"(b1));
}

// ---------------- prep: fold params (tiny, few blocks) ----------------
__global__ void unit_gcn_prep(const float* __restrict__ pA,
                              const float* __restrict__ pPA1,
                              const float* __restrict__ pPA2,
                              const float* __restrict__ pWc,
                              const float* __restrict__ pbc,
                              const float* __restrict__ pgamma,
                              const float* __restrict__ pbeta,
                              const float* __restrict__ prmean,
                              const float* __restrict__ prvar) {
    int tid = blockIdx.x * blockDim.x + threadIdx.x;

    // W fragments for GEMM2 B operand (col-major KxN), hi/lo bf16 (as R5).
    for (int i = tid; i < S_ * 4 * 8 * 32; i += blockDim.x * gridDim.x) {
        int lane = i & 31;
        int ntg  = (i >> 5) & 7;
        int kt   = (i >> 8) & 3;
        int s    = i >> 10;
        int n  = ntg * 8 + (lane >> 2);
        int k0 = kt * 16 + (lane & 3) * 2;
        const float* wr = pWc + (s * 64 + n) * 64;
        float w0 = wr[k0], w1 = wr[k0 + 1], w8 = wr[k0 + 8], w9 = wr[k0 + 9];
        uint32_t h01 = packbf(w1, w0);
        uint32_t h89 = packbf(w9, w8);
        float r0 = w0 - __uint_as_float(h01 << 16);
        float r1 = w1 - __uint_as_float(h01 & 0xffff0000u);
        float r8 = w8 - __uint_as_float(h89 << 16);
        float r9 = w9 - __uint_as_float(h89 & 0xffff0000u);
        uint4 frag;
        frag.x = h01;
        frag.y = h89;
        frag.z = packbf(r1, r0);
        frag.w = packbf(r9, r8);
        g_Wf[i] = frag;
    }

    // Ae^T fragments for GEMM1 A operand (row-major 32x32, m=w, k=v), hi/lo.
    // A1[m][k] = Ae[k][m];  Ae[v][w] = A*PA1+PA2 at (s*25+v)*25+w; OOB = 0.
    for (int i = tid; i < S_ * 2 * 2 * 2 * 32; i += blockDim.x * gridDim.x) {
        int lane = i & 31;
        int hl = (i >> 5) & 1;
        int kt = (i >> 6) & 1;
        int mt = (i >> 7) & 1;
        int s  = i >> 8;
        int gm = mt * 16 + (lane >> 2);
        int k0 = kt * 16 + (lane & 3) * 2;
        float e[8];   // (m, k): (gm,k0),(gm,k0+1),(gm+8,k0),(gm+8,k0+1),
                      //         (gm,k0+8),(gm,k0+9),(gm+8,k0+8),(gm+8,k0+9)
        int ms[2] = {gm, gm + 8};
        int ks[4] = {k0, k0 + 1, k0 + 8, k0 + 9};
#pragma unroll
        for (int kk = 0; kk < 4; kk++)
#pragma unroll
            for (int mm = 0; mm < 2; mm++) {
                int m = ms[mm], k = ks[kk];
                float v = 0.0f;
                if (m < V_ && k < V_) {
                    int idx = (s * V_ + k) * V_ + m;
                    v = pA[idx] * pPA1[idx] + pPA2[idx];
                }
                e[kk * 2 + mm] = v;
            }
        if (hl) {
#pragma unroll
            for (int q = 0; q < 8; q++) {
                float h = __bfloat162float(__float2bfloat16(e[q]));
                e[q] = e[q] - h;
            }
        }
        uint4 frag;
        frag.x = packbf(e[2 * 1 + 0 /*gm,k0+1*/], e[0]);          // a0: row gm,  k0/k0+1
        frag.y = packbf(e[3], e[1]);                              // a1: row gm+8
        frag.z = packbf(e[6], e[4]);                              // a2: row gm,  k0+8/9
        frag.w = packbf(e[7], e[5]);                              // a3: row gm+8
        g_Af[i] = frag;
    }

    // BN fold: out = gemm*alpha + bshift (+x, relu). Bias folded into bshift.
    if (tid < C_) {
        float sc = pgamma[tid] / sqrtf(prvar[tid] + 1e-5f);
        float btot = pbc[tid] + pbc[64 + tid] + pbc[128 + tid];
        g_ab[tid] = sc;
        g_ab[64 + tid] = btot * sc + (pbeta[tid] - prmean[tid] * sc);
    }
}

// ---------------- main fused kernel ----------------
// smem layout (floats)
#define AB_O   0                      // 128: alpha|bshift
#define A2H_O  128                    // 32 x 136 = 4352 (GEMM2 A hi, bf16x2 words)
#define A2L_O  4480                   // 4352 (lo)
#define XBH_O  8832                   // 16 x 264 = 4224 (GEMM1 B hi)
#define XBL_O  13056                  // 4224 (lo)
#define XS_O   17280                  // 64*4*27 = 6912 (fp32 residual)
#define SMEM_FLOATS 24192
#define SMEM_BYTES  (SMEM_FLOATS * 4) // 96768 -> 2 CTAs/SM

__global__ void __launch_bounds__(NTHREADS, 2)
unit_gcn_main(const float* __restrict__ x, float* __restrict__ out) {
    const int n  = blockIdx.y;
    const int bx = blockIdx.x;       // t-tile
    const int t0 = bx * TT;
    const int tid = threadIdx.x;
    const int wid = tid >> 5;
    const int lane = tid & 31;

    extern __shared__ float sm[];
    float* ab = sm + AB_O;
    uint32_t* a2h = (uint32_t*)(sm + A2H_O);
    uint32_t* a2l = (uint32_t*)(sm + A2L_O);
    uint32_t* xbh = (uint32_t*)(sm + XBH_O);
    uint32_t* xbl = (uint32_t*)(sm + XBL_O);
    float* xs = sm + XS_O;

    // Stage BN constants
    if (tid < 128) ab[tid] = g_ab[tid];

    // Zero xsb pad rows 12..15 (v >= 24 partial / pad)
    for (int i = tid; i < 4 * 264; i += NTHREADS) {
        xbh[12 * 264 + i] = 0u;
        xbl[12 * 264 + i] = 0u;
    }

    // Stage x tile: fp32 residual copy + k-packed bf16 hi/lo for GEMM1 B.
    // B1[v][tt*64+c]; word [v/2][n], halves by v&1.
    {
        const float4* xp = (const float4*)x;
        __nv_bfloat16* bh = (__nv_bfloat16*)xbh;
        __nv_bfloat16* bl = (__nv_bfloat16*)xbl;
        for (int q = tid; q < 1600; q += NTHREADS) {
            int c = q / 25;
            int f = q % 25;
            float4 val = xp[(n * 64 + c) * 1875 + bx * 25 + f];
            int p0 = f * 4;
            float vv[4] = {val.x, val.y, val.z, val.w};
#pragma unroll
            for (int j = 0; j < 4; j++) {
                int p = p0 + j;
                int tt = p / 25;
                int w = p - tt * 25;        // joint index v
                float v = vv[j];
                xs[(c * 4 + tt) * 27 + w] = v;
                __nv_bfloat16 h = __float2bfloat16(v);
                __nv_bfloat16 l = __float2bfloat16(v - __bfloat162float(h));
                int half = ((w >> 1) * 264 + tt * 64 + c) * 2 + (w & 1);
                bh[half] = h;
                bl[half] = l;
            }
        }
    }
    __syncthreads();

    // GEMM2 warp coords (R5 layout): wy -> m rows, wx -> n channels
    const int wy = wid & 3;
    const int wx = wid >> 2;

    float acc[2][4][4];
#pragma unroll
    for (int i = 0; i < 2; i++)
#pragma unroll
        for (int j = 0; j < 4; j++)
#pragma unroll
            for (int q = 0; q < 4; q++) acc[i][j][q] = 0.0f;

#pragma unroll
    for (int s = 0; s < S_; s++) {
        // ======== GEMM1: D1[w, tt*64+c] = Ae^T . xs  (M=32,N=256,K=32) ========
        // warp owns n-slice [wid*32, wid*32+32)
        {
            uint4 AH[2][2], AL[2][2];
#pragma unroll
            for (int mt = 0; mt < 2; mt++)
#pragma unroll
                for (int kt = 0; kt < 2; kt++) {
                    AH[mt][kt] = __ldg(g_Af + ((((s * 2 + mt) * 2 + kt) * 2 + 0) * 32) + lane);
                    AL[mt][kt] = __ldg(g_Af + ((((s * 2 + mt) * 2 + kt) * 2 + 1) * 32) + lane);
                }

            float d1[2][4][4];
#pragma unroll
            for (int i = 0; i < 2; i++)
#pragma unroll
                for (int j = 0; j < 4; j++)
#pragma unroll
                    for (int q = 0; q < 4; q++) d1[i][j][q] = 0.0f;

#pragma unroll
            for (int kt = 0; kt < 2; kt++) {
                const int rb = kt * 8 + (lane & 3);
#pragma unroll
                for (int nt = 0; nt < 4; nt++) {
                    const int nn = wid * 32 + nt * 8 + (lane >> 2);
                    uint32_t bh0 = xbh[rb * 264 + nn];
                    uint32_t bh1 = xbh[(rb + 4) * 264 + nn];
                    uint32_t bl0 = xbl[rb * 264 + nn];
                    uint32_t bl1 = xbl[(rb + 4) * 264 + nn];
#pragma unroll
                    for (int mt = 0; mt < 2; mt++) {
                        mma16816(d1[mt][nt], (const uint32_t*)&AH[mt][kt], bh0, bh1);
                        mma16816(d1[mt][nt], (const uint32_t*)&AL[mt][kt], bh0, bh1);
                        mma16816(d1[mt][nt], (const uint32_t*)&AH[mt][kt], bl0, bl1);
                    }
                }
            }

            // ---- pack D1 pairs (adjacent channels) into GEMM2 A layout ----
#pragma unroll
            for (int nt = 0; nt < 4; nt++) {
                const int n0 = wid * 32 + nt * 8 + (lane & 3) * 2;
                const int cw = (n0 & 63) >> 1;     // channel pair = A2 row
                const int tt = n0 >> 6;
#pragma unroll
                for (int mt = 0; mt < 2; mt++) {
                    const int gm = mt * 16 + (lane >> 2);
                    const float* dd = d1[mt][nt];
                    if (gm < V_) {
                        int m2 = tt * 25 + gm;
                        uint32_t h = packbf(dd[1], dd[0]);
                        float r0 = dd[0] - __uint_as_float(h << 16);
                        float r1 = dd[1] - __uint_as_float(h & 0xffff0000u);
                        a2h[cw * 136 + m2] = h;
                        a2l[cw * 136 + m2] = packbf(r1, r0);
                    }
                    if (gm + 8 < V_) {
                        int m2 = tt * 25 + gm + 8;
                        uint32_t h = packbf(dd[3], dd[2]);
                        float r0 = dd[2] - __uint_as_float(h << 16);
                        float r1 = dd[3] - __uint_as_float(h & 0xffff0000u);
                        a2h[cw * 136 + m2] = h;
                        a2l[cw * 136 + m2] = packbf(r1, r0);
                    }
                }
            }
        }
        __syncthreads();   // A2 tiles ready

        // ======== GEMM2: acc[m=col][o] += xa^T . W  (M=128,N=64,K=64) ========
        {
            const uint4* wfs = g_Wf + (s * 4) * 8 * 32 + lane;
#pragma unroll
            for (int kt = 0; kt < 4; kt++) {
                uint4 Bf[4];
#pragma unroll
                for (int j = 0; j < 4; j++)
                    Bf[j] = __ldg(wfs + (kt * 8 + wx * 4 + j) * 32);

                const int kr = kt * 8 + (lane & 3);
#pragma unroll
                for (int mti = 0; mti < 2; mti++) {
                    if (!(wy == 3 && mti == 1)) {   // tile 7 (rows 112..127) dead
                        const int m = (wy * 2 + mti) * 16 + (lane >> 2);
                        uint32_t ah[4], al[4];
                        ah[0] = a2h[kr * 136 + m];
                        ah[1] = a2h[kr * 136 + m + 8];
                        ah[2] = a2h[(kr + 4) * 136 + m];
                        ah[3] = a2h[(kr + 4) * 136 + m + 8];
                        al[0] = a2l[kr * 136 + m];
                        al[1] = a2l[kr * 136 + m + 8];
                        al[2] = a2l[(kr + 4) * 136 + m];
                        al[3] = a2l[(kr + 4) * 136 + m + 8];
#pragma unroll
                        for (int j = 0; j < 4; j++) {
                            mma16816(acc[mti][j], ah, Bf[j].x, Bf[j].y);
                            mma16816(acc[mti][j], al, Bf[j].x, Bf[j].y);
                            mma16816(acc[mti][j], ah, Bf[j].z, Bf[j].w);
                        }
                    }
                }
            }
        }
        if (s < S_ - 1) __syncthreads();   // before next s overwrites A2
    }

    // -------- Epilogue: BN + residual + relu, store --------
    const int nb = wx * 32 + (lane & 3) * 2;
    float alv[8], bsv[8];
#pragma unroll
    for (int j = 0; j < 4; j++) {
        alv[2 * j]     = ab[nb + j * 8];
        alv[2 * j + 1] = ab[nb + j * 8 + 1];
        bsv[2 * j]     = ab[64 + nb + j * 8];
        bsv[2 * j + 1] = ab[64 + nb + j * 8 + 1];
    }

#pragma unroll
    for (int mti = 0; mti < 2; mti++) {
#pragma unroll
        for (int half = 0; half < 2; half++) {
            int m = (wy * 2 + mti) * 16 + (lane >> 2) + half * 8;
            if (m < COLS) {
                int tt = m / 25;
                int w  = m - tt * 25;
                int base = n * 480000 + (t0 + tt) * 25 + w;
                const float* xsr = xs + tt * 27 + w;
#pragma unroll
                for (int j = 0; j < 4; j++) {
                    int o0 = nb + j * 8;
                    float c0 = acc[mti][j][half * 2];
                    float c1 = acc[mti][j][half * 2 + 1];
                    float r0 = xsr[o0 * 108];          // xs[(o0*4+tt)*27+w]
                    float r1 = xsr[(o0 + 1) * 108];
                    float y0 = fmaf(c0, alv[2 * j], bsv[2 * j]) + r0;
                    float y1 = fmaf(c1, alv[2 * j + 1], bsv[2 * j + 1]) + r1;
                    out[base + o0 * 7500]       = fmaxf(y0, 0.0f);
                    out[base + (o0 + 1) * 7500] = fmaxf(y1, 0.0f);
                }
            }
        }
    }
}

extern "C" void kernel_launch(void* const* d_in, const int* in_sizes, int n_in,
                              void* d_out, int out_size) {
    const float* x     = (const float*)d_in[0];
    const float* A     = (const float*)d_in[1];
    const float* PA1   = (const float*)d_in[2];
    const float* PA2   = (const float*)d_in[3];
    const float* Wc    = (const float*)d_in[4];
    const float* bc    = (const float*)d_in[5];
    const float* gamma = (const float*)d_in[6];
    const float* beta  = (const float*)d_in[7];
    const float* rmean = (const float*)d_in[8];
    const float* rvar  = (const float*)d_in[9];
    float* out = (float*)d_out;

    unit_gcn_prep<<<8, 256>>>(A, PA1, PA2, Wc, bc, gamma, beta, rmean, rvar);

    cudaFuncSetAttribute(unit_gcn_main,
                         cudaFuncAttributeMaxDynamicSharedMemorySize, SMEM_BYTES);
    dim3 grid(TBLK, N_);
    unit_gcn_main<<<grid, NTHREADS, SMEM_BYTES>>>(x, out);
}